// round 5
// baseline (speedup 1.0000x reference)
#include <cuda_runtime.h>
#include <cstdint>
#include <cstddef>

#define NORB   9
#define NATOMS 384
#define NEDGES 6144
#define NKP    4
#define ALLN   (NATOMS * NORB)              // 3456
#define NFEAT  58
#define NCPLX  ((size_t)NKP * ALLN * ALLN)  // 47,775,744 = 4*3456*3456

// Static feature -> (row, col, factor) maps for upper-tri orbital pairs
// l = [0,1,2], dims = [1,3,5], offsets = [0,1,4]
__constant__ unsigned char cROWS[NFEAT] = {
    0,
    0,0,0,
    0,0,0,0,0,
    1,1,1,2,2,2,3,3,3,
    1,1,1,1,1,2,2,2,2,2,3,3,3,3,3,
    4,4,4,4,4,5,5,5,5,5,6,6,6,6,6,7,7,7,7,7,8,8,8,8,8
};
__constant__ unsigned char cCOLS[NFEAT] = {
    0,
    1,2,3,
    4,5,6,7,8,
    1,2,3,1,2,3,1,2,3,
    4,5,6,7,8,4,5,6,7,8,4,5,6,7,8,
    4,5,6,7,8,4,5,6,7,8,4,5,6,7,8,4,5,6,7,8,4,5,6,7,8
};
__constant__ float cFACS[NFEAT] = {
    0.5f,
    1.f,1.f,1.f,
    1.f,1.f,1.f,1.f,1.f,
    0.5f,0.5f,0.5f,0.5f,0.5f,0.5f,0.5f,0.5f,0.5f,
    1.f,1.f,1.f,1.f,1.f,1.f,1.f,1.f,1.f,1.f,1.f,1.f,1.f,1.f,1.f,
    0.5f,0.5f,0.5f,0.5f,0.5f,0.5f,0.5f,0.5f,0.5f,0.5f,0.5f,0.5f,0.5f,
    0.5f,0.5f,0.5f,0.5f,0.5f,0.5f,0.5f,0.5f,0.5f,0.5f,0.5f,0.5f
};

// Zero-fill exactly n_u4 uint4s (16B each). Grid-stride.
__global__ void hr2hk_zero(uint4* __restrict__ out, size_t n_u4) {
    for (size_t i = (size_t)blockIdx.x * blockDim.x + threadIdx.x;
         i < n_u4; i += (size_t)gridDim.x * blockDim.x) {
        out[i] = make_uint4(0u, 0u, 0u, 0u);
    }
}

// ---------------- float32 (real part) output path ----------------
// Output buffer: [4, 3456, 3456] float32 = real(H), H = B + B^H.
// Re contribution of phase*val at (r,c) and of conj(phase)*val at (c,r) are
// both val*cos(2*pi*k.R) -> two scalar atomic adds of the same value.
__global__ __launch_bounds__(256, 8) void hr2hk_scatter_real(
    const float* __restrict__ hop,     // [E, 58]
    const float* __restrict__ ons,     // [N, 58]
    const float* __restrict__ kpts,    // [4, 3]
    const int*   __restrict__ eidx,    // [2, E]
    const int*   __restrict__ eshift,  // [E, 3]
    float*       __restrict__ out)     // [4, 3456, 3456] float32
{
    const int w = blockIdx.x;
    const int t = threadIdx.x;
    if (t >= NFEAT * NKP) return;

    const int f = t >> 2;
    const int k = t & 3;
    const bool is_edge = (w < NEDGES);

    int ai, aj;
    float ph;  // Re[exp(-2*pi*i k.R)] = cos(2*pi k.R)
    if (is_edge) {
        ai = eidx[w];
        aj = eidx[NEDGES + w];
        const float d = kpts[k * 3 + 0] * (float)eshift[w * 3 + 0]
                      + kpts[k * 3 + 1] * (float)eshift[w * 3 + 1]
                      + kpts[k * 3 + 2] * (float)eshift[w * 3 + 2];
        ph = cosf(6.283185307179586f * d);
    } else {
        ai = w - NEDGES;
        aj = ai;
        ph = 1.f;
    }
    if ((unsigned)ai >= NATOMS || (unsigned)aj >= NATOMS) return;

    const float* __restrict__ src =
        is_edge ? (hop + (size_t)w * NFEAT)
                : (ons + (size_t)(w - NEDGES) * NFEAT);
    const float re = cFACS[f] * src[f] * ph;

    const int r = ai * NORB + (int)cROWS[f];
    const int c = aj * NORB + (int)cCOLS[f];
    const size_t kbase = (size_t)k * ALLN * ALLN;

    atomicAdd(out + kbase + (size_t)r * ALLN + c, re);  // Re(B) at (r,c)
    atomicAdd(out + kbase + (size_t)c * ALLN + r, re);  // Re(B^H) at (c,r)
}

// ---------------- complex64 (interleaved) output path (fallback) ----------------
__global__ __launch_bounds__(256, 8) void hr2hk_scatter_cplx(
    const float* __restrict__ hop,
    const float* __restrict__ ons,
    const float* __restrict__ kpts,
    const int*   __restrict__ eidx,
    const int*   __restrict__ eshift,
    float*       __restrict__ out)     // [4, 3456, 3456] complex64 as float pairs
{
    const int w = blockIdx.x;
    const int t = threadIdx.x;
    if (t >= NFEAT * NKP) return;

    const int f = t >> 2;
    const int k = t & 3;
    const bool is_edge = (w < NEDGES);

    int ai, aj;
    float pre, pim;
    if (is_edge) {
        ai = eidx[w];
        aj = eidx[NEDGES + w];
        const float d = kpts[k * 3 + 0] * (float)eshift[w * 3 + 0]
                      + kpts[k * 3 + 1] * (float)eshift[w * 3 + 1]
                      + kpts[k * 3 + 2] * (float)eshift[w * 3 + 2];
        float s, c;
        __sincosf(6.283185307179586f * d, &s, &c);
        pre = c; pim = -s;
    } else {
        ai = w - NEDGES; aj = ai; pre = 1.f; pim = 0.f;
    }
    if ((unsigned)ai >= NATOMS || (unsigned)aj >= NATOMS) return;

    const float* __restrict__ src =
        is_edge ? (hop + (size_t)w * NFEAT)
                : (ons + (size_t)(w - NEDGES) * NFEAT);
    const float val = cFACS[f] * src[f];
    const float re = val * pre, im = val * pim;

    const int r = ai * NORB + (int)cROWS[f];
    const int c = aj * NORB + (int)cCOLS[f];
    const size_t kbase = (size_t)k * ALLN * ALLN;

    float* p0 = out + 2 * (kbase + (size_t)r * ALLN + c);
    float* p1 = out + 2 * (kbase + (size_t)c * ALLN + r);
    atomicAdd(p0 + 0, re);
    atomicAdd(p0 + 1, im);
    atomicAdd(p1 + 0, re);
    atomicAdd(p1 + 1, -im);
}

extern "C" void kernel_launch(void* const* d_in, const int* in_sizes, int n_in,
                              void* d_out, int out_size) {
    // Identify inputs by (pairwise-distinct) element counts, not position.
    const float* hop    = nullptr;
    const float* ons    = nullptr;
    const float* kpts   = nullptr;
    const int*   eidx   = nullptr;
    const int*   eshift = nullptr;

    for (int i = 0; i < n_in; ++i) {
        switch (in_sizes[i]) {
            case NEDGES * NFEAT: hop    = (const float*)d_in[i]; break;  // 356352
            case NATOMS * NFEAT: ons    = (const float*)d_in[i]; break;  // 22272
            case NKP * 3:        kpts   = (const float*)d_in[i]; break;  // 12
            case 2 * NEDGES:     eidx   = (const int*)d_in[i];   break;  // 12288
            case NEDGES * 3:     eshift = (const int*)d_in[i];   break;  // 18432
            default: break;
        }
    }
    if (!hop || !ons || !kpts || !eidx || !eshift) return;

    if ((long long)out_size == (long long)NCPLX) {
        // out is [4,3456,3456] float32 (real part): buffer = NCPLX*4 bytes.
        hr2hk_zero<<<8192, 256>>>((uint4*)d_out, NCPLX * 4 / 16);
        hr2hk_scatter_real<<<NEDGES + NATOMS, 256>>>(
            hop, ons, kpts, eidx, eshift, (float*)d_out);
    } else if ((long long)out_size == 2LL * (long long)NCPLX) {
        // out is complex64 flattened to float pairs: buffer = NCPLX*8 bytes.
        hr2hk_zero<<<8192, 256>>>((uint4*)d_out, NCPLX * 8 / 16);
        hr2hk_scatter_cplx<<<NEDGES + NATOMS, 256>>>(
            hop, ons, kpts, eidx, eshift, (float*)d_out);
    }
    // Any other out_size: launch nothing -> harness reports "0 nodes",
    // which is a diagnostic signal that the shape model is wrong.
}